// round 14
// baseline (speedup 1.0000x reference)
#include <cuda_runtime.h>
#include <cuda_fp16.h>
#include <math.h>
#include <stdint.h>

// Problem dims (fixed)
#define BB   8
#define TT   4096
#define DD   512
#define HH   512
#define MM   (BB*TT)          // 32768 rows
#define NN   (2*HH)           // 1024 gemm cols
#define KK   DD               // 512

// Chunked scan config
#define CNK  64
#define CL   (TT/CNK)         // 64
#define NSEQ (BB*HH)          // 4096

#define TILES_PER_B 256       // 8 cols x 32 rowblocks per batch
#define S3_PER_B    32        // scan3 items per batch (chunk-pairs)

// ---------------- scratch ----------------
__device__ __align__(16) __half g_xn[(size_t)MM * DD];   // 32 MB
__device__ __align__(16) __half g_Wt[(size_t)NN * KK];   // 1 MB
__device__ __align__(16) __half2 g_cv[(size_t)MM * HH];  // 64 MB packed (c,v)
__device__ float g_A [CNK * NSEQ];
__device__ float g_Bc[CNK * NSEQ];
__device__ float g_P [CNK * NSEQ];
// sync state (re-initialized every call)
__device__ int g_s3t[BB];      // per-batch scan3 ticket counters
__device__ int g_btc[BB];      // per-batch tile countdown
__device__ int g_bready[BB];   // per-batch scan2-done flag

// ---------------- helpers ----------------
#define CP_ASYNC16(dst, src) \
    asm volatile("cp.async.cg.shared.global [%0], [%1], 16;" :: "r"(dst), "l"(src))
#define CP_COMMIT() asm volatile("cp.async.commit_group;" ::: "memory")
#define CP_WAIT0()  asm volatile("cp.async.wait_group 0;" ::: "memory")
#define CP_WAIT1()  asm volatile("cp.async.wait_group 1;" ::: "memory")

#define MMA_F16(d, a, b) \
    asm volatile("mma.sync.aligned.m16n8k16.row.col.f32.f16.f16.f32 " \
        "{%0,%1,%2,%3}, {%4,%5,%6,%7}, {%8,%9}, {%0,%1,%2,%3};" \
        : "+f"((d)[0]), "+f"((d)[1]), "+f"((d)[2]), "+f"((d)[3]) \
        : "r"((a)[0]), "r"((a)[1]), "r"((a)[2]), "r"((a)[3]), \
          "r"((b)[0]), "r"((b)[1]))

#define LDSM4(R0, R1, R2, R3, addr) \
    asm volatile("ldmatrix.sync.aligned.m8n8.x4.shared.b16 {%0,%1,%2,%3}, [%4];" \
        : "=r"(R0), "=r"(R1), "=r"(R2), "=r"(R3) : "r"(addr))

// ---------------- 1. LayerNorm (outputs fp16) ----------------
__global__ void __launch_bounds__(128) ln_kernel(const float* __restrict__ x,
                                                 const float* __restrict__ gamma,
                                                 const float* __restrict__ beta) {
    const int row = blockIdx.x;
    const int tid = threadIdx.x;
    const float4* xr = (const float4*)(x + (size_t)row * DD);
    float4 v = xr[tid];
    float s  = v.x + v.y + v.z + v.w;
    float ss = v.x*v.x + v.y*v.y + v.z*v.z + v.w*v.w;
    #pragma unroll
    for (int o = 16; o; o >>= 1) {
        s  += __shfl_xor_sync(0xffffffffu, s,  o);
        ss += __shfl_xor_sync(0xffffffffu, ss, o);
    }
    __shared__ float sh[8];
    const int w = tid >> 5, l = tid & 31;
    if (l == 0) { sh[w] = s; sh[4 + w] = ss; }
    __syncthreads();
    if (tid == 0) {
        float S  = sh[0] + sh[1] + sh[2] + sh[3];
        float SS = sh[4] + sh[5] + sh[6] + sh[7];
        float mu  = S * (1.0f / DD);
        float var = SS * (1.0f / DD) - mu * mu;
        sh[0] = mu;
        sh[1] = rsqrtf(var + 1e-10f);
    }
    __syncthreads();
    const float mu = sh[0], rs = sh[1];
    float4 g  = ((const float4*)gamma)[tid];
    float4 bb = ((const float4*)beta)[tid];
    __half2 o01 = __floats2half2_rn((v.x - mu) * rs * g.x + bb.x,
                                    (v.y - mu) * rs * g.y + bb.y);
    __half2 o23 = __floats2half2_rn((v.z - mu) * rs * g.z + bb.z,
                                    (v.w - mu) * rs * g.w + bb.w);
    __half2* dst = (__half2*)(g_xn + (size_t)row * DD);
    dst[2 * tid]     = o01;
    dst[2 * tid + 1] = o23;
}

// ---------------- 1b. init + W transpose/interleave ----------------
__global__ void __launch_bounds__(256) init_wt_kernel(const float* __restrict__ W) {
    const int idx = blockIdx.x * 256 + threadIdx.x;   // < NN*KK
    if (blockIdx.x == 0) {
        const int t = threadIdx.x;
        if (t < BB) { g_btc[t] = TILES_PER_B; g_bready[t] = 0; g_s3t[t] = 0; }
    }
    const int np = idx >> 9;
    const int k  = idx & 511;
    const int h  = np >> 1;
    const int gs = np & 1;
    g_Wt[idx] = __float2half_rn(W[(size_t)k * NN + gs * HH + h]);
}

// ---------------- 2. GEMM config ----------------
#define BM 128
#define BN 128
#define BK 64
#define NSTG (KK / BK)           // 8
#define ROWB 144                  // bytes per smem row (72 halves)
#define TILEB (BM * ROWB)         // 18432
#define NBUF 3
#define SMEM_BYTES (2 * NBUF * TILEB)   // 110592

// A rows stored PERMUTED: smem slot p = mi*16 + rr*8 + g holds logical row
//   g*8 + mi*2 + rr  (within each 64-row warp block)
__device__ __forceinline__ void load_stage(const __half* __restrict__ Ag,
                                           const __half* __restrict__ Bg,
                                           uint32_t sA, uint32_t sB,
                                           int k0, int tid) {
    #pragma unroll
    for (int i = 0; i < 4; i++) {                 // A: 128 rows x 64 halves
        int q  = tid + i * 256;
        int ms = q >> 3, k8 = q & 7;
        int srow = (ms & 64) | (((ms & 7) << 3) + (((ms >> 4) & 3) << 1) + ((ms >> 3) & 1));
        CP_ASYNC16(sA + ms * ROWB + k8 * 16,
                   Ag + (size_t)srow * KK + k0 + k8 * 8);
    }
    #pragma unroll
    for (int i = 0; i < 4; i++) {                 // B: 128 rows x 64 halves
        int q = tid + i * 256;
        int n = q >> 3, k8 = q & 7;
        CP_ASYNC16(sB + n * ROWB + k8 * 16,
                   Bg + (size_t)n * KK + k0 + k8 * 8);
    }
}

// ---------------- scan2 for one batch (inline, 256 threads) -------------------
__device__ void do_scan2(int b, float* __restrict__ hidden, int tid) {
    const int L = tid & 7;
    #pragma unroll 1
    for (int pass = 0; pass < 16; pass++) {
        const int seq = b * HH + pass * 32 + (tid >> 3);
        float a[8], bb[8];
        #pragma unroll
        for (int i = 0; i < 8; i++) {
            a [i] = __ldcg(&g_A [(L * 8 + i) * NSEQ + seq]);
            bb[i] = __ldcg(&g_Bc[(L * 8 + i) * NSEQ + seq]);
        }
        float CA = 1.0f, CB = 0.0f;
        #pragma unroll
        for (int i = 0; i < 8; i++) { CB = fmaf(a[i], CB, bb[i]); CA *= a[i]; }
        #pragma unroll
        for (int d = 1; d < 8; d <<= 1) {
            float pA = __shfl_up_sync(0xffffffffu, CA, d, 8);
            float pB = __shfl_up_sync(0xffffffffu, CB, d, 8);
            if (L >= d) { CB = fmaf(CA, pB, CB); CA *= pA; }
        }
        float pB = __shfl_up_sync(0xffffffffu, CB, 1, 8);
        float p = (L == 0) ? 0.0f : pB;
        #pragma unroll
        for (int i = 0; i < 8; i++) {
            g_P[(L * 8 + i) * NSEQ + seq] = p;
            p = fmaf(a[i], p, bb[i]);
        }
        if (L == 7) hidden[seq] = p;
    }
}

// ---------------- scan3 item: (batch, chunk-pair); 128 thr per chunk ----------
__device__ void do_scan3(int item, const float* __restrict__ x,
                         float* __restrict__ out, int tid) {
    const int b  = item >> 5;
    const int ci = ((item & 31) << 1) + (tid >> 7);
    const int h4 = (tid & 127) << 2;            // 4 h per thread
    const int seq0 = b * HH + h4;
    float hs0 = __ldcg(&g_P[ci * NSEQ + seq0]);
    float hs1 = __ldcg(&g_P[ci * NSEQ + seq0 + 1]);
    float hs2 = __ldcg(&g_P[ci * NSEQ + seq0 + 2]);
    float hs3 = __ldcg(&g_P[ci * NSEQ + seq0 + 3]);
    size_t off = ((size_t)(b * TT + ci * CL)) * HH + h4;
    #pragma unroll 4
    for (int l = 0; l < CL; l++) {
        uint4 cvp = __ldcg((const uint4*)(g_cv + off));
        float2 cv0 = __half22float2(*(__half2*)&cvp.x);
        float2 cv1 = __half22float2(*(__half2*)&cvp.y);
        float2 cv2 = __half22float2(*(__half2*)&cvp.z);
        float2 cv3 = __half22float2(*(__half2*)&cvp.w);
        float4 xv = *(const float4*)(x + off);
        hs0 = fmaf(cv0.x, hs0, cv0.y);
        hs1 = fmaf(cv1.x, hs1, cv1.y);
        hs2 = fmaf(cv2.x, hs2, cv2.y);
        hs3 = fmaf(cv3.x, hs3, cv3.y);
        float4 ov = { hs0 + xv.x, hs1 + xv.y, hs2 + xv.z, hs3 + xv.w };
        *(float4*)(out + off) = ov;
        off += HH;
    }
}

// ---------------- 2. fp16 GEMM + fused act/chunk-scan + NON-BLOCKING steal ----
__global__ void __launch_bounds__(256, 2) gemm_kernel(const float* __restrict__ x,
                                                      float* __restrict__ hidden,
                                                      float* __restrict__ out) {
    extern __shared__ char sm[];
    const int tid  = threadIdx.x;
    const int lane = tid & 31;
    const int grp  = lane >> 2;
    const int q4   = lane & 3;
    const int wid  = tid >> 5;          // 8 warps: 2 (M) x 4 (N)
    const int wm   = wid & 1;
    const int wn   = wid >> 1;
    const int rowBase = blockIdx.y * BM;
    const int colBase = blockIdx.x * BN;

    const __half* Ag = g_xn + (size_t)rowBase * KK;
    const __half* Bg = g_Wt + (size_t)colBase * KK;

    uint32_t sbase = (uint32_t)__cvta_generic_to_shared(sm);
    uint32_t sA[NBUF], sB[NBUF];
    #pragma unroll
    for (int i = 0; i < NBUF; i++) {
        sA[i] = sbase + (2 * i) * TILEB;
        sB[i] = sbase + (2 * i + 1) * TILEB;
    }

    uint32_t aoff[4], boff[2];
    #pragma unroll
    for (int mi = 0; mi < 4; mi++)
        aoff[mi] = (wm * 64 + mi * 16 + (lane & 15)) * ROWB + (lane >> 4) * 16;
    #pragma unroll
    for (int p = 0; p < 2; p++)
        boff[p] = (wn * 32 + p * 16 + ((lane >> 4) << 3) + (lane & 7)) * ROWB
                  + (((lane >> 3) & 1) << 4);

    float acc[4][4][4];
    #pragma unroll
    for (int i = 0; i < 4; i++)
        #pragma unroll
        for (int j = 0; j < 4; j++)
            #pragma unroll
            for (int p = 0; p < 4; p++) acc[i][j][p] = 0.0f;

    load_stage(Ag, Bg, sA[0], sB[0], 0, tid);
    CP_COMMIT();
    load_stage(Ag, Bg, sA[1], sB[1], BK, tid);
    CP_COMMIT();

    #pragma unroll 1
    for (int s = 0; s < NSTG; s++) {
        if (s == NSTG - 1) { CP_WAIT0(); } else { CP_WAIT1(); }
        __syncthreads();
        if (s + 2 < NSTG) {
            load_stage(Ag, Bg, sA[(s+2)%NBUF], sB[(s+2)%NBUF], (s + 2) * BK, tid);
            CP_COMMIT();
        }
        const uint32_t Ab = sA[s % NBUF];
        const uint32_t Bb = sB[s % NBUF];
        #pragma unroll
        for (int k16 = 0; k16 < 4; k16++) {
            uint32_t a[4][4], b[4][2];
            #pragma unroll
            for (int mi = 0; mi < 4; mi++)
                LDSM4(a[mi][0], a[mi][1], a[mi][2], a[mi][3],
                      Ab + aoff[mi] + k16 * 32);
            #pragma unroll
            for (int p = 0; p < 2; p++)
                LDSM4(b[2*p][0], b[2*p][1], b[2*p+1][0], b[2*p+1][1],
                      Bb + boff[p] + k16 * 32);
            #pragma unroll
            for (int mi = 0; mi < 4; mi++)
                #pragma unroll
                for (int ni = 0; ni < 4; ni++)
                    MMA_F16(acc[mi][ni], a[mi], b[ni]);
        }
    }

    // Epilogue: acc pairs = (k_gate, h_pre) of one h channel; fused chunk scan.
    const int hBase = (colBase >> 1) + wn * 16;
    const int mWarp = rowBase + wm * 64;
    const int bIdx  = rowBase >> 12;
    const int ci    = ((rowBase & (TT - 1)) >> 6) + wm;
    #pragma unroll
    for (int ni = 0; ni < 4; ni++) {
        const int h = hBase + ni * 4 + q4;
        float GA = 1.0f, GB = 0.0f;
        #pragma unroll
        for (int mi = 0; mi < 4; mi++) {
            #pragma unroll
            for (int rr = 0; rr < 2; rr++) {
                float k  = acc[mi][ni][2 * rr];
                float hp = acc[mi][ni][2 * rr + 1];
                k = fminf(fmaxf(k, -30.0f), 30.0f);
                float ek = __expf(k);
                float c  = 1.0f / (1.0f + ek);       // sigmoid(-k)
                float z  = ek * c;                    // sigmoid(k)
                float g  = (hp >= 0.0f) ? (hp + 0.5f)
                                        : (1.0f / (1.0f + __expf(-hp)));
                float v  = z * g;
                const int m = mWarp + grp * 8 + mi * 2 + rr;
                g_cv[(size_t)m * HH + h] = __floats2half2_rn(c, v);
                GB = fmaf(c, GB, v);
                GA *= c;
            }
        }
        #pragma unroll
        for (int s = 1; s < 8; s <<= 1) {
            float a2 = __shfl_down_sync(0xffffffffu, GA, 4 * s);
            float b2 = __shfl_down_sync(0xffffffffu, GB, 4 * s);
            GB = fmaf(GB, a2, b2);
            GA *= a2;
        }
        if (grp == 0) {
            g_A [ci * NSEQ + bIdx * HH + h] = GA;
            g_Bc[ci * NSEQ + bIdx * HH + h] = GB;
        }
    }

    // ---- batch countdown: last tile runs scan2, then raises ready flag ----
    __shared__ int s_flag;
    __threadfence();
    __syncthreads();
    if (tid == 0) s_flag = (atomicSub(&g_btc[bIdx], 1) == 1);
    __syncthreads();
    if (s_flag) {
        do_scan2(bIdx, hidden, tid);
        __threadfence();
        __syncthreads();
        if (tid == 0) atomicExch(&g_bready[bIdx], 1);
    }

    // ---- NON-BLOCKING steal: drain prior batch's scan3 pool if ready ----
    if (bIdx > 0) {
        const int pb = bIdx - 1;
        if (tid == 0) s_flag = atomicAdd(&g_bready[pb], 0);
        __syncthreads();
        const int rdy = s_flag;
        __syncthreads();
        if (rdy) {
            for (;;) {
                if (tid == 0) s_flag = atomicAdd(&g_s3t[pb], 1);
                __syncthreads();
                const int t = s_flag;
                __syncthreads();
                if (t >= S3_PER_B) break;
                do_scan3(pb * S3_PER_B + t, x, out, tid);
                __syncthreads();
            }
        }
    }
    // never wait: exit immediately, freeing the SM slot
}

// ---------------- drain: finish remaining scan3 items (same counters) ---------
__global__ void __launch_bounds__(256) drain_kernel(const float* __restrict__ x,
                                                    float* __restrict__ out) {
    __shared__ int s_flag;
    const int tid = threadIdx.x;
    for (int b = 0; b < BB; b++) {
        for (;;) {
            if (tid == 0) s_flag = atomicAdd(&g_s3t[b], 1);
            __syncthreads();
            const int t = s_flag;
            __syncthreads();
            if (t >= S3_PER_B) break;
            do_scan3(b * S3_PER_B + t, x, out, tid);
            __syncthreads();
        }
    }
}

// ---------------- launch ----------------
extern "C" void kernel_launch(void* const* d_in, const int* in_sizes, int n_in,
                              void* d_out, int out_size) {
    const float* x     = (const float*)d_in[0];
    const float* gamma = (const float*)d_in[1];
    const float* beta  = (const float*)d_in[2];
    const float* W     = (const float*)d_in[3];
    float* out    = (float*)d_out;
    float* hidden = out + (size_t)MM * DD;

    cudaFuncSetAttribute(gemm_kernel, cudaFuncAttributeMaxDynamicSharedMemorySize,
                         SMEM_BYTES);

    init_wt_kernel<<<(NN * KK) / 256, 256>>>(W);
    ln_kernel<<<MM, 128>>>(x, gamma, beta);
    gemm_kernel<<<dim3(NN / BN, MM / BM), 256, SMEM_BYTES>>>(x, hidden, out);
    drain_kernel<<<148, 256>>>(x, out);
}

// round 15
// speedup vs baseline: 6.6009x; 6.6009x over previous
#include <cuda_runtime.h>
#include <cuda_fp16.h>
#include <math.h>
#include <stdint.h>

// Problem dims (fixed)
#define BB   8
#define TT   4096
#define DD   512
#define HH   512
#define MM   (BB*TT)          // 32768 rows
#define NN   (2*HH)           // 1024 gemm cols
#define KK   DD               // 512

// Chunked scan config
#define CNK  64
#define CL   (TT/CNK)         // 64
#define NSEQ (BB*HH)          // 4096

// ---------------- scratch ----------------
__device__ __align__(16) __half g_xn[(size_t)MM * DD];   // 32 MB
__device__ __align__(16) __half g_Wt[(size_t)NN * KK];   // 1 MB
__device__ __align__(16) __half2 g_cv[(size_t)MM * HH];  // 64 MB packed (c,v)
__device__ float g_A [CNK * NSEQ];
__device__ float g_Bc[CNK * NSEQ];
__device__ float g_P [CNK * NSEQ];

// ---------------- helpers ----------------
#define CP_ASYNC16(dst, src) \
    asm volatile("cp.async.cg.shared.global [%0], [%1], 16;" :: "r"(dst), "l"(src))
#define CP_COMMIT() asm volatile("cp.async.commit_group;" ::: "memory")
#define CP_WAIT0()  asm volatile("cp.async.wait_group 0;" ::: "memory")
#define CP_WAIT1()  asm volatile("cp.async.wait_group 1;" ::: "memory")

#define MMA_F16(d, a, b) \
    asm volatile("mma.sync.aligned.m16n8k16.row.col.f32.f16.f16.f32 " \
        "{%0,%1,%2,%3}, {%4,%5,%6,%7}, {%8,%9}, {%0,%1,%2,%3};" \
        : "+f"((d)[0]), "+f"((d)[1]), "+f"((d)[2]), "+f"((d)[3]) \
        : "r"((a)[0]), "r"((a)[1]), "r"((a)[2]), "r"((a)[3]), \
          "r"((b)[0]), "r"((b)[1]))

#define LDSM4(R0, R1, R2, R3, addr) \
    asm volatile("ldmatrix.sync.aligned.m8n8.x4.shared.b16 {%0,%1,%2,%3}, [%4];" \
        : "=r"(R0), "=r"(R1), "=r"(R2), "=r"(R3) : "r"(addr))

// ---------------- 1. LayerNorm (outputs fp16) ----------------
__global__ void __launch_bounds__(128) ln_kernel(const float* __restrict__ x,
                                                 const float* __restrict__ gamma,
                                                 const float* __restrict__ beta) {
    const int row = blockIdx.x;
    const int tid = threadIdx.x;
    const float4* xr = (const float4*)(x + (size_t)row * DD);
    float4 v = xr[tid];
    float s  = v.x + v.y + v.z + v.w;
    float ss = v.x*v.x + v.y*v.y + v.z*v.z + v.w*v.w;
    #pragma unroll
    for (int o = 16; o; o >>= 1) {
        s  += __shfl_xor_sync(0xffffffffu, s,  o);
        ss += __shfl_xor_sync(0xffffffffu, ss, o);
    }
    __shared__ float sh[8];
    const int w = tid >> 5, l = tid & 31;
    if (l == 0) { sh[w] = s; sh[4 + w] = ss; }
    __syncthreads();
    if (tid == 0) {
        float S  = sh[0] + sh[1] + sh[2] + sh[3];
        float SS = sh[4] + sh[5] + sh[6] + sh[7];
        float mu  = S * (1.0f / DD);
        float var = SS * (1.0f / DD) - mu * mu;
        sh[0] = mu;
        sh[1] = rsqrtf(var + 1e-10f);
    }
    __syncthreads();
    const float mu = sh[0], rs = sh[1];
    float4 g  = ((const float4*)gamma)[tid];
    float4 bb = ((const float4*)beta)[tid];
    __half2 o01 = __floats2half2_rn((v.x - mu) * rs * g.x + bb.x,
                                    (v.y - mu) * rs * g.y + bb.y);
    __half2 o23 = __floats2half2_rn((v.z - mu) * rs * g.z + bb.z,
                                    (v.w - mu) * rs * g.w + bb.w);
    __half2* dst = (__half2*)(g_xn + (size_t)row * DD);
    dst[2 * tid]     = o01;
    dst[2 * tid + 1] = o23;
}

// ---------------- 1b. W transpose+interleave: g_Wt[2h+g][k] = W[k][g*HH+h] -----
__global__ void __launch_bounds__(256) wt_kernel(const float* __restrict__ W) {
    const int idx = blockIdx.x * 256 + threadIdx.x;   // < NN*KK
    const int np = idx >> 9;
    const int k  = idx & 511;
    const int h  = np >> 1;
    const int gs = np & 1;
    g_Wt[idx] = __float2half_rn(W[(size_t)k * NN + gs * HH + h]);
}

// ---------------- 2. fp16 GEMM (ldmatrix, 3-stage) + fused act + chunk scan ----
#define BM 128
#define BN 128
#define BK 64
#define NSTG (KK / BK)           // 8
#define ROWB 144                  // bytes per smem row (72 halves)
#define TILEB (BM * ROWB)         // 18432
#define NBUF 3
#define SMEM_BYTES (2 * NBUF * TILEB)   // 110592

// A rows stored PERMUTED: smem slot p = mi*16 + rr*8 + g holds logical row
//   g*8 + mi*2 + rr  (within each 64-row warp block)
__device__ __forceinline__ void load_stage(const __half* __restrict__ Ag,
                                           const __half* __restrict__ Bg,
                                           uint32_t sA, uint32_t sB,
                                           int k0, int tid) {
    #pragma unroll
    for (int i = 0; i < 4; i++) {                 // A: 128 rows x 64 halves
        int q  = tid + i * 256;
        int ms = q >> 3, k8 = q & 7;
        int srow = (ms & 64) | (((ms & 7) << 3) + (((ms >> 4) & 3) << 1) + ((ms >> 3) & 1));
        CP_ASYNC16(sA + ms * ROWB + k8 * 16,
                   Ag + (size_t)srow * KK + k0 + k8 * 8);
    }
    #pragma unroll
    for (int i = 0; i < 4; i++) {                 // B: 128 rows x 64 halves
        int q = tid + i * 256;
        int n = q >> 3, k8 = q & 7;
        CP_ASYNC16(sB + n * ROWB + k8 * 16,
                   Bg + (size_t)n * KK + k0 + k8 * 8);
    }
}

__global__ void __launch_bounds__(256, 2) gemm_kernel() {
    extern __shared__ char sm[];
    const int tid  = threadIdx.x;
    const int lane = tid & 31;
    const int grp  = lane >> 2;
    const int q4   = lane & 3;
    const int wid  = tid >> 5;          // 8 warps: 2 (M) x 4 (N)
    const int wm   = wid & 1;
    const int wn   = wid >> 1;
    const int rowBase = blockIdx.y * BM;
    const int colBase = blockIdx.x * BN;

    const __half* Ag = g_xn + (size_t)rowBase * KK;
    const __half* Bg = g_Wt + (size_t)colBase * KK;

    uint32_t sbase = (uint32_t)__cvta_generic_to_shared(sm);
    uint32_t sA[NBUF], sB[NBUF];
    #pragma unroll
    for (int i = 0; i < NBUF; i++) {
        sA[i] = sbase + (2 * i) * TILEB;
        sB[i] = sbase + (2 * i + 1) * TILEB;
    }

    uint32_t aoff[4], boff[2];
    #pragma unroll
    for (int mi = 0; mi < 4; mi++)
        aoff[mi] = (wm * 64 + mi * 16 + (lane & 15)) * ROWB + (lane >> 4) * 16;
    #pragma unroll
    for (int p = 0; p < 2; p++)
        boff[p] = (wn * 32 + p * 16 + ((lane >> 4) << 3) + (lane & 7)) * ROWB
                  + (((lane >> 3) & 1) << 4);

    float acc[4][4][4];
    #pragma unroll
    for (int i = 0; i < 4; i++)
        #pragma unroll
        for (int j = 0; j < 4; j++)
            #pragma unroll
            for (int p = 0; p < 4; p++) acc[i][j][p] = 0.0f;

    load_stage(Ag, Bg, sA[0], sB[0], 0, tid);
    CP_COMMIT();
    load_stage(Ag, Bg, sA[1], sB[1], BK, tid);
    CP_COMMIT();

    #pragma unroll 1
    for (int s = 0; s < NSTG; s++) {
        if (s == NSTG - 1) { CP_WAIT0(); } else { CP_WAIT1(); }
        __syncthreads();
        if (s + 2 < NSTG) {
            load_stage(Ag, Bg, sA[(s+2)%NBUF], sB[(s+2)%NBUF], (s + 2) * BK, tid);
            CP_COMMIT();
        }
        const uint32_t Ab = sA[s % NBUF];
        const uint32_t Bb = sB[s % NBUF];
        #pragma unroll
        for (int k16 = 0; k16 < 4; k16++) {
            uint32_t a[4][4], b[4][2];
            #pragma unroll
            for (int mi = 0; mi < 4; mi++)
                LDSM4(a[mi][0], a[mi][1], a[mi][2], a[mi][3],
                      Ab + aoff[mi] + k16 * 32);
            #pragma unroll
            for (int p = 0; p < 2; p++)
                LDSM4(b[2*p][0], b[2*p][1], b[2*p+1][0], b[2*p+1][1],
                      Bb + boff[p] + k16 * 32);
            #pragma unroll
            for (int mi = 0; mi < 4; mi++)
                #pragma unroll
                for (int ni = 0; ni < 4; ni++)
                    MMA_F16(acc[mi][ni], a[mi], b[ni]);
        }
    }

    // Epilogue: acc pairs (c0,c1)/(c2,c3) = (k_gate, h_pre) of one h channel.
    // Thread owns 8 consecutive timesteps per column -> fused chunk composition.
    const int hBase = (colBase >> 1) + wn * 16;
    const int mWarp = rowBase + wm * 64;
    const int bIdx  = rowBase >> 12;
    const int ci    = ((rowBase & (TT - 1)) >> 6) + wm;
    #pragma unroll
    for (int ni = 0; ni < 4; ni++) {
        const int h = hBase + ni * 4 + q4;
        float GA = 1.0f, GB = 0.0f;
        #pragma unroll
        for (int mi = 0; mi < 4; mi++) {
            #pragma unroll
            for (int rr = 0; rr < 2; rr++) {
                float k  = acc[mi][ni][2 * rr];
                float hp = acc[mi][ni][2 * rr + 1];
                k = fminf(fmaxf(k, -30.0f), 30.0f);
                float ek = __expf(k);
                float c  = 1.0f / (1.0f + ek);       // sigmoid(-k)
                float z  = ek * c;                    // sigmoid(k)
                float g  = (hp >= 0.0f) ? (hp + 0.5f)
                                        : (1.0f / (1.0f + __expf(-hp)));
                float v  = z * g;
                const int m = mWarp + grp * 8 + mi * 2 + rr;
                g_cv[(size_t)m * HH + h] = __floats2half2_rn(c, v);
                GB = fmaf(c, GB, v);
                GA *= c;
            }
        }
        #pragma unroll
        for (int s = 1; s < 8; s <<= 1) {
            float a2 = __shfl_down_sync(0xffffffffu, GA, 4 * s);
            float b2 = __shfl_down_sync(0xffffffffu, GB, 4 * s);
            GB = fmaf(GB, a2, b2);
            GA *= a2;
        }
        if (grp == 0) {
            g_A [ci * NSEQ + bIdx * HH + h] = GA;
            g_Bc[ci * NSEQ + bIdx * HH + h] = GB;
        }
    }
}

// ---------------- 5. Scan phase 2: warp-parallel (8 lanes per seq) -------------
__global__ void __launch_bounds__(256) scan2_kernel(float* __restrict__ hidden) {
    const int t   = blockIdx.x * 256 + threadIdx.x;   // < NSEQ * 8
    const int L   = t & 7;                             // chunk-octet lane
    const int seq = t >> 3;
    float a[8], b[8];
    #pragma unroll
    for (int i = 0; i < 8; i++) {
        a[i] = g_A [(L * 8 + i) * NSEQ + seq];
        b[i] = g_Bc[(L * 8 + i) * NSEQ + seq];
    }
    float CA = 1.0f, CB = 0.0f;
    #pragma unroll
    for (int i = 0; i < 8; i++) { CB = fmaf(a[i], CB, b[i]); CA *= a[i]; }
    // inclusive scan across the 8 lanes (chunk order ascending)
    #pragma unroll
    for (int d = 1; d < 8; d <<= 1) {
        float pA = __shfl_up_sync(0xffffffffu, CA, d, 8);
        float pB = __shfl_up_sync(0xffffffffu, CB, d, 8);
        if (L >= d) { CB = fmaf(CA, pB, CB); CA *= pA; }
    }
    // exclusive entering state (h0 = 0 -> state = B of exclusive composite)
    float pB = __shfl_up_sync(0xffffffffu, CB, 1, 8);
    float p = (L == 0) ? 0.0f : pB;
    #pragma unroll
    for (int i = 0; i < 8; i++) {
        g_P[(L * 8 + i) * NSEQ + seq] = p;
        p = fmaf(a[i], p, b[i]);
    }
    if (L == 7) hidden[seq] = p;
}

// ---------------- 6. Scan phase 3: apply prefix, out = h + x (float4) ----------
__global__ void __launch_bounds__(256) scan3_kernel(const float* __restrict__ x,
                                                    float* __restrict__ out) {
    const int item = blockIdx.x;                 // 256 items: (batch, chunk-pair)
    const int tid  = threadIdx.x;
    const int b  = item >> 5;
    const int ci = ((item & 31) << 1) + (tid >> 7);
    const int h4 = (tid & 127) << 2;             // 4 h per thread
    const int seq0 = b * HH + h4;
    float hs0 = g_P[ci * NSEQ + seq0];
    float hs1 = g_P[ci * NSEQ + seq0 + 1];
    float hs2 = g_P[ci * NSEQ + seq0 + 2];
    float hs3 = g_P[ci * NSEQ + seq0 + 3];
    size_t off = ((size_t)(b * TT + ci * CL)) * HH + h4;
    #pragma unroll 4
    for (int l = 0; l < CL; l++) {
        uint4 cvp = *(const uint4*)(g_cv + off);
        float2 cv0 = __half22float2(*(__half2*)&cvp.x);
        float2 cv1 = __half22float2(*(__half2*)&cvp.y);
        float2 cv2 = __half22float2(*(__half2*)&cvp.z);
        float2 cv3 = __half22float2(*(__half2*)&cvp.w);
        float4 xv = *(const float4*)(x + off);
        hs0 = fmaf(cv0.x, hs0, cv0.y);
        hs1 = fmaf(cv1.x, hs1, cv1.y);
        hs2 = fmaf(cv2.x, hs2, cv2.y);
        hs3 = fmaf(cv3.x, hs3, cv3.y);
        float4 ov = { hs0 + xv.x, hs1 + xv.y, hs2 + xv.z, hs3 + xv.w };
        *(float4*)(out + off) = ov;
        off += HH;
    }
}

// ---------------- launch ----------------
extern "C" void kernel_launch(void* const* d_in, const int* in_sizes, int n_in,
                              void* d_out, int out_size) {
    const float* x     = (const float*)d_in[0];
    const float* gamma = (const float*)d_in[1];
    const float* beta  = (const float*)d_in[2];
    const float* W     = (const float*)d_in[3];
    float* out    = (float*)d_out;
    float* hidden = out + (size_t)MM * DD;

    cudaFuncSetAttribute(gemm_kernel, cudaFuncAttributeMaxDynamicSharedMemorySize,
                         SMEM_BYTES);

    ln_kernel  <<<MM, 128>>>(x, gamma, beta);
    wt_kernel  <<<(NN * KK) / 256, 256>>>(W);
    gemm_kernel<<<dim3(NN / BN, MM / BM), 256, SMEM_BYTES>>>();
    scan2_kernel<<<(NSEQ * 8) / 256, 256>>>(hidden);
    scan3_kernel<<<256, 256>>>(x, out);
}

// round 16
// speedup vs baseline: 7.0810x; 1.0727x over previous
#include <cuda_runtime.h>
#include <cuda_fp16.h>
#include <math.h>
#include <stdint.h>

// Problem dims (fixed)
#define BB   8
#define TT   4096
#define DD   512
#define HH   512
#define MM   (BB*TT)          // 32768 rows
#define NN   (2*HH)           // 1024 gemm cols
#define KK   DD               // 512

// Chunked scan config
#define CNK  64
#define CL   (TT/CNK)         // 64
#define NSEQ (BB*HH)          // 4096

// ---------------- scratch ----------------
__device__ __align__(16) __half g_xn[(size_t)MM * DD];   // 32 MB
__device__ __align__(16) __half g_Wt[(size_t)NN * KK];   // 1 MB
__device__ __align__(16) __half2 g_cv[(size_t)MM * HH];  // 64 MB packed (c,v)
__device__ float g_A [CNK * NSEQ];
__device__ float g_Bc[CNK * NSEQ];
__device__ float g_P [CNK * NSEQ];

// ---------------- helpers ----------------
#define CP_ASYNC16(dst, src) \
    asm volatile("cp.async.cg.shared.global [%0], [%1], 16;" :: "r"(dst), "l"(src))
#define CP_COMMIT() asm volatile("cp.async.commit_group;" ::: "memory")
#define CP_WAIT0()  asm volatile("cp.async.wait_group 0;" ::: "memory")
#define CP_WAIT1()  asm volatile("cp.async.wait_group 1;" ::: "memory")

// fp16-accumulate MMA: D(f16x2 x2) += A x B
#define MMA_F16ACC(d, a, b) \
    asm volatile("mma.sync.aligned.m16n8k16.row.col.f16.f16.f16.f16 " \
        "{%0,%1}, {%2,%3,%4,%5}, {%6,%7}, {%0,%1};" \
        : "+r"((d)[0]), "+r"((d)[1]) \
        : "r"((a)[0]), "r"((a)[1]), "r"((a)[2]), "r"((a)[3]), \
          "r"((b)[0]), "r"((b)[1]))

#define LDSM4(R0, R1, R2, R3, addr) \
    asm volatile("ldmatrix.sync.aligned.m8n8.x4.shared.b16 {%0,%1,%2,%3}, [%4];" \
        : "=r"(R0), "=r"(R1), "=r"(R2), "=r"(R3) : "r"(addr))

// ---------------- 1. LayerNorm (outputs fp16) ----------------
__global__ void __launch_bounds__(128) ln_kernel(const float* __restrict__ x,
                                                 const float* __restrict__ gamma,
                                                 const float* __restrict__ beta) {
    const int row = blockIdx.x;
    const int tid = threadIdx.x;
    const float4* xr = (const float4*)(x + (size_t)row * DD);
    float4 v = xr[tid];
    float s  = v.x + v.y + v.z + v.w;
    float ss = v.x*v.x + v.y*v.y + v.z*v.z + v.w*v.w;
    #pragma unroll
    for (int o = 16; o; o >>= 1) {
        s  += __shfl_xor_sync(0xffffffffu, s,  o);
        ss += __shfl_xor_sync(0xffffffffu, ss, o);
    }
    __shared__ float sh[8];
    const int w = tid >> 5, l = tid & 31;
    if (l == 0) { sh[w] = s; sh[4 + w] = ss; }
    __syncthreads();
    if (tid == 0) {
        float S  = sh[0] + sh[1] + sh[2] + sh[3];
        float SS = sh[4] + sh[5] + sh[6] + sh[7];
        float mu  = S * (1.0f / DD);
        float var = SS * (1.0f / DD) - mu * mu;
        sh[0] = mu;
        sh[1] = rsqrtf(var + 1e-10f);
    }
    __syncthreads();
    const float mu = sh[0], rs = sh[1];
    float4 g  = ((const float4*)gamma)[tid];
    float4 bb = ((const float4*)beta)[tid];
    __half2 o01 = __floats2half2_rn((v.x - mu) * rs * g.x + bb.x,
                                    (v.y - mu) * rs * g.y + bb.y);
    __half2 o23 = __floats2half2_rn((v.z - mu) * rs * g.z + bb.z,
                                    (v.w - mu) * rs * g.w + bb.w);
    __half2* dst = (__half2*)(g_xn + (size_t)row * DD);
    dst[2 * tid]     = o01;
    dst[2 * tid + 1] = o23;
}

// ---------------- 1b. W transpose+interleave: g_Wt[2h+g][k] = W[k][g*HH+h] -----
__global__ void __launch_bounds__(256) wt_kernel(const float* __restrict__ W) {
    const int idx = blockIdx.x * 256 + threadIdx.x;   // < NN*KK
    const int np = idx >> 9;
    const int k  = idx & 511;
    const int h  = np >> 1;
    const int gs = np & 1;
    g_Wt[idx] = __float2half_rn(W[(size_t)k * NN + gs * HH + h]);
}

// ---------------- 2. fp16 GEMM (f16 accum, ldmatrix, 3-stage) ------------------
#define BM 128
#define BN 128
#define BK 64
#define NSTG (KK / BK)           // 8
#define ROWB 144                  // bytes per smem row (72 halves)
#define TILEB (BM * ROWB)         // 18432
#define NBUF 3
#define SMEM_BYTES (2 * NBUF * TILEB)   // 110592

// A rows stored PERMUTED: smem slot p = mi*16 + rr*8 + g holds logical row
//   g*8 + mi*2 + rr  (within each 64-row warp block)
__device__ __forceinline__ void load_stage(const __half* __restrict__ Ag,
                                           const __half* __restrict__ Bg,
                                           uint32_t sA, uint32_t sB,
                                           int k0, int tid) {
    #pragma unroll
    for (int i = 0; i < 4; i++) {                 // A: 128 rows x 64 halves
        int q  = tid + i * 256;
        int ms = q >> 3, k8 = q & 7;
        int srow = (ms & 64) | (((ms & 7) << 3) + (((ms >> 4) & 3) << 1) + ((ms >> 3) & 1));
        CP_ASYNC16(sA + ms * ROWB + k8 * 16,
                   Ag + (size_t)srow * KK + k0 + k8 * 8);
    }
    #pragma unroll
    for (int i = 0; i < 4; i++) {                 // B: 128 rows x 64 halves
        int q = tid + i * 256;
        int n = q >> 3, k8 = q & 7;
        CP_ASYNC16(sB + n * ROWB + k8 * 16,
                   Bg + (size_t)n * KK + k0 + k8 * 8);
    }
}

// one K=64 stage of MMAs into the given f16 accumulator set
__device__ __forceinline__ void mma_stage(uint32_t Ab, uint32_t Bb,
                                          const uint32_t* aoff, const uint32_t* boff,
                                          uint32_t acch[4][4][2]) {
    #pragma unroll
    for (int k16 = 0; k16 < 4; k16++) {
        uint32_t a[4][4], b[4][2];
        #pragma unroll
        for (int mi = 0; mi < 4; mi++)
            LDSM4(a[mi][0], a[mi][1], a[mi][2], a[mi][3],
                  Ab + aoff[mi] + k16 * 32);
        #pragma unroll
        for (int p = 0; p < 2; p++)
            LDSM4(b[2*p][0], b[2*p][1], b[2*p+1][0], b[2*p+1][1],
                  Bb + boff[p] + k16 * 32);
        #pragma unroll
        for (int mi = 0; mi < 4; mi++)
            #pragma unroll
            for (int ni = 0; ni < 4; ni++)
                MMA_F16ACC(acch[mi][ni], a[mi], b[ni]);
    }
}

__global__ void __launch_bounds__(256, 2) gemm_kernel() {
    extern __shared__ char sm[];
    const int tid  = threadIdx.x;
    const int lane = tid & 31;
    const int grp  = lane >> 2;
    const int q4   = lane & 3;
    const int wid  = tid >> 5;          // 8 warps: 2 (M) x 4 (N)
    const int wm   = wid & 1;
    const int wn   = wid >> 1;
    const int rowBase = blockIdx.y * BM;
    const int colBase = blockIdx.x * BN;

    const __half* Ag = g_xn + (size_t)rowBase * KK;
    const __half* Bg = g_Wt + (size_t)colBase * KK;

    uint32_t sbase = (uint32_t)__cvta_generic_to_shared(sm);
    uint32_t sA[NBUF], sB[NBUF];
    #pragma unroll
    for (int i = 0; i < NBUF; i++) {
        sA[i] = sbase + (2 * i) * TILEB;
        sB[i] = sbase + (2 * i + 1) * TILEB;
    }

    uint32_t aoff[4], boff[2];
    #pragma unroll
    for (int mi = 0; mi < 4; mi++)
        aoff[mi] = (wm * 64 + mi * 16 + (lane & 15)) * ROWB + (lane >> 4) * 16;
    #pragma unroll
    for (int p = 0; p < 2; p++)
        boff[p] = (wn * 32 + p * 16 + ((lane >> 4) << 3) + (lane & 7)) * ROWB
                  + (((lane >> 3) & 1) << 4);

    // two f16 accumulator sets (even / odd stages), summed in f32 at epilogue
    uint32_t acchE[4][4][2] = {};
    uint32_t acchO[4][4][2] = {};

    load_stage(Ag, Bg, sA[0], sB[0], 0, tid);
    CP_COMMIT();
    load_stage(Ag, Bg, sA[1], sB[1], BK, tid);
    CP_COMMIT();

    #pragma unroll 1
    for (int s = 0; s < NSTG; s += 2) {
        // even sub-stage s
        if (s == NSTG - 1) { CP_WAIT0(); } else { CP_WAIT1(); }
        __syncthreads();
        if (s + 2 < NSTG) {
            load_stage(Ag, Bg, sA[(s+2)%NBUF], sB[(s+2)%NBUF], (s + 2) * BK, tid);
            CP_COMMIT();
        }
        mma_stage(sA[s % NBUF], sB[s % NBUF], aoff, boff, acchE);
        // odd sub-stage s+1
        if (s + 1 == NSTG - 1) { CP_WAIT0(); } else { CP_WAIT1(); }
        __syncthreads();
        if (s + 3 < NSTG) {
            load_stage(Ag, Bg, sA[(s+3)%NBUF], sB[(s+3)%NBUF], (s + 3) * BK, tid);
            CP_COMMIT();
        }
        mma_stage(sA[(s+1) % NBUF], sB[(s+1) % NBUF], aoff, boff, acchO);
    }

    // Epilogue: f16x2 accum pair (lo,hi) = (k_gate, h_pre) of one h channel.
    // Thread owns 8 consecutive timesteps per column -> fused chunk composition.
    const int hBase = (colBase >> 1) + wn * 16;
    const int mWarp = rowBase + wm * 64;
    const int bIdx  = rowBase >> 12;
    const int ci    = ((rowBase & (TT - 1)) >> 6) + wm;
    #pragma unroll
    for (int ni = 0; ni < 4; ni++) {
        const int h = hBase + ni * 4 + q4;
        float GA = 1.0f, GB = 0.0f;
        #pragma unroll
        for (int mi = 0; mi < 4; mi++) {
            #pragma unroll
            for (int rr = 0; rr < 2; rr++) {
                float2 e2 = __half22float2(*(__half2*)&acchE[mi][ni][rr]);
                float2 o2 = __half22float2(*(__half2*)&acchO[mi][ni][rr]);
                float k  = e2.x + o2.x;
                float hp = e2.y + o2.y;
                k = fminf(fmaxf(k, -30.0f), 30.0f);
                float ek = __expf(k);
                float c  = 1.0f / (1.0f + ek);       // sigmoid(-k)
                float z  = ek * c;                    // sigmoid(k)
                float g  = (hp >= 0.0f) ? (hp + 0.5f)
                                        : (1.0f / (1.0f + __expf(-hp)));
                float v  = z * g;
                const int m = mWarp + grp * 8 + mi * 2 + rr;
                g_cv[(size_t)m * HH + h] = __floats2half2_rn(c, v);
                GB = fmaf(c, GB, v);
                GA *= c;
            }
        }
        #pragma unroll
        for (int s = 1; s < 8; s <<= 1) {
            float a2 = __shfl_down_sync(0xffffffffu, GA, 4 * s);
            float b2 = __shfl_down_sync(0xffffffffu, GB, 4 * s);
            GB = fmaf(GB, a2, b2);
            GA *= a2;
        }
        if (grp == 0) {
            g_A [ci * NSEQ + bIdx * HH + h] = GA;
            g_Bc[ci * NSEQ + bIdx * HH + h] = GB;
        }
    }
}

// ---------------- 5. Scan phase 2: warp-parallel (8 lanes per seq) -------------
__global__ void __launch_bounds__(256) scan2_kernel(float* __restrict__ hidden) {
    const int t   = blockIdx.x * 256 + threadIdx.x;   // < NSEQ * 8
    const int L   = t & 7;                             // chunk-octet lane
    const int seq = t >> 3;
    float a[8], b[8];
    #pragma unroll
    for (int i = 0; i < 8; i++) {
        a[i] = g_A [(L * 8 + i) * NSEQ + seq];
        b[i] = g_Bc[(L * 8 + i) * NSEQ + seq];
    }
    float CA = 1.0f, CB = 0.0f;
    #pragma unroll
    for (int i = 0; i < 8; i++) { CB = fmaf(a[i], CB, b[i]); CA *= a[i]; }
    // inclusive scan across the 8 lanes (chunk order ascending)
    #pragma unroll
    for (int d = 1; d < 8; d <<= 1) {
        float pA = __shfl_up_sync(0xffffffffu, CA, d, 8);
        float pB = __shfl_up_sync(0xffffffffu, CB, d, 8);
        if (L >= d) { CB = fmaf(CA, pB, CB); CA *= pA; }
    }
    // exclusive entering state (h0 = 0 -> state = B of exclusive composite)
    float pB = __shfl_up_sync(0xffffffffu, CB, 1, 8);
    float p = (L == 0) ? 0.0f : pB;
    #pragma unroll
    for (int i = 0; i < 8; i++) {
        g_P[(L * 8 + i) * NSEQ + seq] = p;
        p = fmaf(a[i], p, b[i]);
    }
    if (L == 7) hidden[seq] = p;
}

// ---------------- 6. Scan phase 3: apply prefix, out = h + x (float2) ----------
__global__ void __launch_bounds__(256) scan3_kernel(const float* __restrict__ x,
                                                    float* __restrict__ out) {
    const int blk = blockIdx.x;                  // 512 blocks: (batch, chunk)
    const int tid = threadIdx.x;
    const int b  = blk >> 6;
    const int ci = blk & 63;
    const int h2 = tid << 1;                     // 2 h per thread
    const int seq0 = b * HH + h2;
    float hs0 = g_P[ci * NSEQ + seq0];
    float hs1 = g_P[ci * NSEQ + seq0 + 1];
    size_t off = ((size_t)(b * TT + ci * CL)) * HH + h2;
    #pragma unroll 4
    for (int l = 0; l < CL; l++) {
        uint2 cvp = *(const uint2*)(g_cv + off);
        float2 cv0 = __half22float2(*(__half2*)&cvp.x);
        float2 cv1 = __half22float2(*(__half2*)&cvp.y);
        float2 xv = *(const float2*)(x + off);
        hs0 = fmaf(cv0.x, hs0, cv0.y);
        hs1 = fmaf(cv1.x, hs1, cv1.y);
        float2 ov = { hs0 + xv.x, hs1 + xv.y };
        *(float2*)(out + off) = ov;
        off += HH;
    }
}

// ---------------- launch ----------------
extern "C" void kernel_launch(void* const* d_in, const int* in_sizes, int n_in,
                              void* d_out, int out_size) {
    const float* x     = (const float*)d_in[0];
    const float* gamma = (const float*)d_in[1];
    const float* beta  = (const float*)d_in[2];
    const float* W     = (const float*)d_in[3];
    float* out    = (float*)d_out;
    float* hidden = out + (size_t)MM * DD;

    cudaFuncSetAttribute(gemm_kernel, cudaFuncAttributeMaxDynamicSharedMemorySize,
                         SMEM_BYTES);

    ln_kernel  <<<MM, 128>>>(x, gamma, beta);
    wt_kernel  <<<(NN * KK) / 256, 256>>>(W);
    gemm_kernel<<<dim3(NN / BN, MM / BM), 256, SMEM_BYTES>>>();
    scan2_kernel<<<(NSEQ * 8) / 256, 256>>>(hidden);
    scan3_kernel<<<512, 256>>>(x, out);
}

// round 17
// speedup vs baseline: 7.0822x; 1.0002x over previous
#include <cuda_runtime.h>
#include <cuda_fp16.h>
#include <math.h>
#include <stdint.h>

// Problem dims (fixed)
#define BB   8
#define TT   4096
#define DD   512
#define HH   512
#define MM   (BB*TT)          // 32768 rows
#define NN   (2*HH)           // 1024 gemm cols
#define KK   DD               // 512

// Chunked scan config
#define CNK  128
#define CL   (TT/CNK)         // 32
#define NSEQ (BB*HH)          // 4096

// ---------------- scratch ----------------
__device__ __align__(16) __half g_xn[(size_t)MM * DD];   // 32 MB
__device__ __align__(16) __half g_Wt[(size_t)NN * KK];   // 1 MB
__device__ __align__(16) __half2 g_cv[(size_t)MM * HH];  // 64 MB packed (c,v)
__device__ float g_A [CNK * NSEQ];                       // 2 MB
__device__ float g_Bc[CNK * NSEQ];                       // 2 MB
__device__ float g_P [CNK * NSEQ];                       // 2 MB

// ---------------- helpers ----------------
#define CP_ASYNC16(dst, src) \
    asm volatile("cp.async.cg.shared.global [%0], [%1], 16;" :: "r"(dst), "l"(src))
#define CP_COMMIT() asm volatile("cp.async.commit_group;" ::: "memory")
#define CP_WAIT0()  asm volatile("cp.async.wait_group 0;" ::: "memory")
#define CP_WAIT1()  asm volatile("cp.async.wait_group 1;" ::: "memory")

// fp16-accumulate MMA: D(f16x2 x2) += A x B
#define MMA_F16ACC(d, a, b) \
    asm volatile("mma.sync.aligned.m16n8k16.row.col.f16.f16.f16.f16 " \
        "{%0,%1}, {%2,%3,%4,%5}, {%6,%7}, {%0,%1};" \
        : "+r"((d)[0]), "+r"((d)[1]) \
        : "r"((a)[0]), "r"((a)[1]), "r"((a)[2]), "r"((a)[3]), \
          "r"((b)[0]), "r"((b)[1]))

#define LDSM4(R0, R1, R2, R3, addr) \
    asm volatile("ldmatrix.sync.aligned.m8n8.x4.shared.b16 {%0,%1,%2,%3}, [%4];" \
        : "=r"(R0), "=r"(R1), "=r"(R2), "=r"(R3) : "r"(addr))

// ---------------- 1. LayerNorm (outputs fp16) ----------------
__global__ void __launch_bounds__(128) ln_kernel(const float* __restrict__ x,
                                                 const float* __restrict__ gamma,
                                                 const float* __restrict__ beta) {
    const int row = blockIdx.x;
    const int tid = threadIdx.x;
    const float4* xr = (const float4*)(x + (size_t)row * DD);
    float4 v = xr[tid];
    float s  = v.x + v.y + v.z + v.w;
    float ss = v.x*v.x + v.y*v.y + v.z*v.z + v.w*v.w;
    #pragma unroll
    for (int o = 16; o; o >>= 1) {
        s  += __shfl_xor_sync(0xffffffffu, s,  o);
        ss += __shfl_xor_sync(0xffffffffu, ss, o);
    }
    __shared__ float sh[8];
    const int w = tid >> 5, l = tid & 31;
    if (l == 0) { sh[w] = s; sh[4 + w] = ss; }
    __syncthreads();
    if (tid == 0) {
        float S  = sh[0] + sh[1] + sh[2] + sh[3];
        float SS = sh[4] + sh[5] + sh[6] + sh[7];
        float mu  = S * (1.0f / DD);
        float var = SS * (1.0f / DD) - mu * mu;
        sh[0] = mu;
        sh[1] = rsqrtf(var + 1e-10f);
    }
    __syncthreads();
    const float mu = sh[0], rs = sh[1];
    float4 g  = ((const float4*)gamma)[tid];
    float4 bb = ((const float4*)beta)[tid];
    __half2 o01 = __floats2half2_rn((v.x - mu) * rs * g.x + bb.x,
                                    (v.y - mu) * rs * g.y + bb.y);
    __half2 o23 = __floats2half2_rn((v.z - mu) * rs * g.z + bb.z,
                                    (v.w - mu) * rs * g.w + bb.w);
    __half2* dst = (__half2*)(g_xn + (size_t)row * DD);
    dst[2 * tid]     = o01;
    dst[2 * tid + 1] = o23;
}

// ---------------- 1b. W transpose+interleave: g_Wt[2h+g][k] = W[k][g*HH+h] -----
__global__ void __launch_bounds__(256) wt_kernel(const float* __restrict__ W) {
    const int idx = blockIdx.x * 256 + threadIdx.x;   // < NN*KK
    const int np = idx >> 9;
    const int k  = idx & 511;
    const int h  = np >> 1;
    const int gs = np & 1;
    g_Wt[idx] = __float2half_rn(W[(size_t)k * NN + gs * HH + h]);
}

// ---------------- 2. fp16 GEMM (f16 accum, ldmatrix, 3-stage) ------------------
#define BM 128
#define BN 128
#define BK 64
#define NSTG (KK / BK)           // 8
#define ROWB 144                  // bytes per smem row (72 halves)
#define TILEB (BM * ROWB)         // 18432
#define NBUF 3
#define SMEM_BYTES (2 * NBUF * TILEB)   // 110592

// A rows stored PERMUTED: smem slot p = mi*16 + rr*8 + g holds logical row
//   g*8 + mi*2 + rr  (within each 64-row warp block)
__device__ __forceinline__ void load_stage(const __half* __restrict__ Ag,
                                           const __half* __restrict__ Bg,
                                           uint32_t sA, uint32_t sB,
                                           int k0, int tid) {
    #pragma unroll
    for (int i = 0; i < 4; i++) {                 // A: 128 rows x 64 halves
        int q  = tid + i * 256;
        int ms = q >> 3, k8 = q & 7;
        int srow = (ms & 64) | (((ms & 7) << 3) + (((ms >> 4) & 3) << 1) + ((ms >> 3) & 1));
        CP_ASYNC16(sA + ms * ROWB + k8 * 16,
                   Ag + (size_t)srow * KK + k0 + k8 * 8);
    }
    #pragma unroll
    for (int i = 0; i < 4; i++) {                 // B: 128 rows x 64 halves
        int q = tid + i * 256;
        int n = q >> 3, k8 = q & 7;
        CP_ASYNC16(sB + n * ROWB + k8 * 16,
                   Bg + (size_t)n * KK + k0 + k8 * 8);
    }
}

// one K=64 stage of MMAs into the given f16 accumulator set
__device__ __forceinline__ void mma_stage(uint32_t Ab, uint32_t Bb,
                                          const uint32_t* aoff, const uint32_t* boff,
                                          uint32_t acch[4][4][2]) {
    #pragma unroll
    for (int k16 = 0; k16 < 4; k16++) {
        uint32_t a[4][4], b[4][2];
        #pragma unroll
        for (int mi = 0; mi < 4; mi++)
            LDSM4(a[mi][0], a[mi][1], a[mi][2], a[mi][3],
                  Ab + aoff[mi] + k16 * 32);
        #pragma unroll
        for (int p = 0; p < 2; p++)
            LDSM4(b[2*p][0], b[2*p][1], b[2*p+1][0], b[2*p+1][1],
                  Bb + boff[p] + k16 * 32);
        #pragma unroll
        for (int mi = 0; mi < 4; mi++)
            #pragma unroll
            for (int ni = 0; ni < 4; ni++)
                MMA_F16ACC(acch[mi][ni], a[mi], b[ni]);
    }
}

__global__ void __launch_bounds__(256, 2) gemm_kernel() {
    extern __shared__ char sm[];
    const int tid  = threadIdx.x;
    const int lane = tid & 31;
    const int grp  = lane >> 2;
    const int q4   = lane & 3;
    const int wid  = tid >> 5;          // 8 warps: 2 (M) x 4 (N)
    const int wm   = wid & 1;
    const int wn   = wid >> 1;
    const int rowBase = blockIdx.y * BM;
    const int colBase = blockIdx.x * BN;

    const __half* Ag = g_xn + (size_t)rowBase * KK;
    const __half* Bg = g_Wt + (size_t)colBase * KK;

    uint32_t sbase = (uint32_t)__cvta_generic_to_shared(sm);
    uint32_t sA[NBUF], sB[NBUF];
    #pragma unroll
    for (int i = 0; i < NBUF; i++) {
        sA[i] = sbase + (2 * i) * TILEB;
        sB[i] = sbase + (2 * i + 1) * TILEB;
    }

    uint32_t aoff[4], boff[2];
    #pragma unroll
    for (int mi = 0; mi < 4; mi++)
        aoff[mi] = (wm * 64 + mi * 16 + (lane & 15)) * ROWB + (lane >> 4) * 16;
    #pragma unroll
    for (int p = 0; p < 2; p++)
        boff[p] = (wn * 32 + p * 16 + ((lane >> 4) << 3) + (lane & 7)) * ROWB
                  + (((lane >> 3) & 1) << 4);

    // two f16 accumulator sets (even / odd stages), summed in f32 at epilogue
    uint32_t acchE[4][4][2] = {};
    uint32_t acchO[4][4][2] = {};

    load_stage(Ag, Bg, sA[0], sB[0], 0, tid);
    CP_COMMIT();
    load_stage(Ag, Bg, sA[1], sB[1], BK, tid);
    CP_COMMIT();

    #pragma unroll 1
    for (int s = 0; s < NSTG; s += 2) {
        // even sub-stage s
        if (s == NSTG - 1) { CP_WAIT0(); } else { CP_WAIT1(); }
        __syncthreads();
        if (s + 2 < NSTG) {
            load_stage(Ag, Bg, sA[(s+2)%NBUF], sB[(s+2)%NBUF], (s + 2) * BK, tid);
            CP_COMMIT();
        }
        mma_stage(sA[s % NBUF], sB[s % NBUF], aoff, boff, acchE);
        // odd sub-stage s+1
        if (s + 1 == NSTG - 1) { CP_WAIT0(); } else { CP_WAIT1(); }
        __syncthreads();
        if (s + 3 < NSTG) {
            load_stage(Ag, Bg, sA[(s+3)%NBUF], sB[(s+3)%NBUF], (s + 3) * BK, tid);
            CP_COMMIT();
        }
        mma_stage(sA[(s+1) % NBUF], sB[(s+1) % NBUF], aoff, boff, acchO);
    }

    // Epilogue: f16x2 accum pair (lo,hi) = (k_gate, h_pre) of one h channel.
    // Thread owns 8 consecutive timesteps (grp*8..grp*8+7 within the 64-row
    // warp block) -> fused 32-step chunk composition: butterfly over 2 steps,
    // lanes grp==0 / grp==4 hold chunks [0,32) / [32,64) of the warp block.
    const int hBase = (colBase >> 1) + wn * 16;
    const int mWarp = rowBase + wm * 64;
    const int bIdx  = rowBase >> 12;
    const int ciBase = ((rowBase & (TT - 1)) >> 5) + wm * 2;   // 32-t chunks
    #pragma unroll
    for (int ni = 0; ni < 4; ni++) {
        const int h = hBase + ni * 4 + q4;
        float GA = 1.0f, GB = 0.0f;
        #pragma unroll
        for (int mi = 0; mi < 4; mi++) {
            #pragma unroll
            for (int rr = 0; rr < 2; rr++) {
                float2 e2 = __half22float2(*(__half2*)&acchE[mi][ni][rr]);
                float2 o2 = __half22float2(*(__half2*)&acchO[mi][ni][rr]);
                float k  = e2.x + o2.x;
                float hp = e2.y + o2.y;
                k = fminf(fmaxf(k, -30.0f), 30.0f);
                float ek = __expf(k);
                float c  = 1.0f / (1.0f + ek);       // sigmoid(-k)
                float z  = ek * c;                    // sigmoid(k)
                float g  = (hp >= 0.0f) ? (hp + 0.5f)
                                        : (1.0f / (1.0f + __expf(-hp)));
                float v  = z * g;
                const int m = mWarp + grp * 8 + mi * 2 + rr;
                g_cv[(size_t)m * HH + h] = __floats2half2_rn(c, v);
                GB = fmaf(c, GB, v);
                GA *= c;
            }
        }
        // 2-step down-butterfly: lane grp g composes grps g..g+3 (t ascending)
        #pragma unroll
        for (int s = 1; s < 4; s <<= 1) {
            float a2 = __shfl_down_sync(0xffffffffu, GA, 4 * s);
            float b2 = __shfl_down_sync(0xffffffffu, GB, 4 * s);
            GB = fmaf(GB, a2, b2);
            GA *= a2;
        }
        if ((grp & 3) == 0) {
            const int ci = ciBase + (grp >> 2);
            g_A [ci * NSEQ + bIdx * HH + h] = GA;
            g_Bc[ci * NSEQ + bIdx * HH + h] = GB;
        }
    }
}

// ---------------- 5. Scan phase 2: warp-parallel (16 lanes per seq) ------------
__global__ void __launch_bounds__(256) scan2_kernel(float* __restrict__ hidden) {
    const int t   = blockIdx.x * 256 + threadIdx.x;   // < NSEQ * 16
    const int L   = t & 15;                            // chunk-octet lane
    const int seq = t >> 4;
    float a[8], b[8];
    #pragma unroll
    for (int i = 0; i < 8; i++) {
        a[i] = g_A [(L * 8 + i) * NSEQ + seq];
        b[i] = g_Bc[(L * 8 + i) * NSEQ + seq];
    }
    float CA = 1.0f, CB = 0.0f;
    #pragma unroll
    for (int i = 0; i < 8; i++) { CB = fmaf(a[i], CB, b[i]); CA *= a[i]; }
    // inclusive scan across the 16 lanes (chunk order ascending)
    #pragma unroll
    for (int d = 1; d < 16; d <<= 1) {
        float pA = __shfl_up_sync(0xffffffffu, CA, d, 16);
        float pB = __shfl_up_sync(0xffffffffu, CB, d, 16);
        if (L >= d) { CB = fmaf(CA, pB, CB); CA *= pA; }
    }
    // exclusive entering state (h0 = 0 -> state = B of exclusive composite)
    float pB = __shfl_up_sync(0xffffffffu, CB, 1, 16);
    float p = (L == 0) ? 0.0f : pB;
    #pragma unroll
    for (int i = 0; i < 8; i++) {
        g_P[(L * 8 + i) * NSEQ + seq] = p;
        p = fmaf(a[i], p, b[i]);
    }
    if (L == 15) hidden[seq] = p;
}

// ---------------- 6. Scan phase 3: apply prefix, out = h + x (float2) ----------
__global__ void __launch_bounds__(256) scan3_kernel(const float* __restrict__ x,
                                                    float* __restrict__ out) {
    const int blk = blockIdx.x;                  // 1024 blocks: (batch, chunk)
    const int tid = threadIdx.x;
    const int b  = blk >> 7;
    const int ci = blk & 127;
    const int h2 = tid << 1;                     // 2 h per thread
    const int seq0 = b * HH + h2;
    float hs0 = g_P[ci * NSEQ + seq0];
    float hs1 = g_P[ci * NSEQ + seq0 + 1];
    size_t off = ((size_t)(b * TT + ci * CL)) * HH + h2;
    #pragma unroll 4
    for (int l = 0; l < CL; l++) {
        uint2 cvp = *(const uint2*)(g_cv + off);
        float2 cv0 = __half22float2(*(__half2*)&cvp.x);
        float2 cv1 = __half22float2(*(__half2*)&cvp.y);
        float2 xv = *(const float2*)(x + off);
        hs0 = fmaf(cv0.x, hs0, cv0.y);
        hs1 = fmaf(cv1.x, hs1, cv1.y);
        float2 ov = { hs0 + xv.x, hs1 + xv.y };
        *(float2*)(out + off) = ov;
        off += HH;
    }
}

// ---------------- launch ----------------
extern "C" void kernel_launch(void* const* d_in, const int* in_sizes, int n_in,
                              void* d_out, int out_size) {
    const float* x     = (const float*)d_in[0];
    const float* gamma = (const float*)d_in[1];
    const float* beta  = (const float*)d_in[2];
    const float* W     = (const float*)d_in[3];
    float* out    = (float*)d_out;
    float* hidden = out + (size_t)MM * DD;

    cudaFuncSetAttribute(gemm_kernel, cudaFuncAttributeMaxDynamicSharedMemorySize,
                         SMEM_BYTES);

    ln_kernel  <<<MM, 128>>>(x, gamma, beta);
    wt_kernel  <<<(NN * KK) / 256, 256>>>(W);
    gemm_kernel<<<dim3(NN / BN, MM / BM), 256, SMEM_BYTES>>>();
    scan2_kernel<<<(NSEQ * 16) / 256, 256>>>(hidden);
    scan3_kernel<<<1024, 256>>>(x, out);
}